// round 1
// baseline (speedup 1.0000x reference)
#include <cuda_runtime.h>
#include <math.h>

#define D_MODEL 512
#define N_HEADS 8
#define HEAD_DIM 64
#define D_FF 2048
#define SEQ 4096
#define BATCH 2
#define ROWS (BATCH*SEQ)      /* 8192 */
#define BH (BATCH*N_HEADS)    /* 16 */

// ---------------- scratch (no allocations allowed) ----------------
__device__ float  g_xln [ROWS*D_MODEL];
__device__ float  g_qkv [ROWS*3*D_MODEL];
__device__ float  g_Q   [BH*SEQ*HEAD_DIM];
__device__ float  g_Kv  [BH*SEQ*HEAD_DIM];
__device__ float  g_Vv  [BH*SEQ*HEAD_DIM];
__device__ float  g_ctx [ROWS*D_MODEL];
__device__ float  g_src2[ROWS*D_MODEL];
__device__ float  g_h   [ROWS*D_FF];
__device__ float2 g_rope[SEQ*32];

// ---------------- LayerNorm: one block per row of 512 ----------------
__global__ void __launch_bounds__(128) ln_kernel(const float* __restrict__ x,
                                                 const float* __restrict__ w,
                                                 const float* __restrict__ b,
                                                 float* __restrict__ y)
{
    int row = blockIdx.x;
    int t = threadIdx.x;
    const float4* xr = reinterpret_cast<const float4*>(x) + (size_t)row * 128;
    float4 v = xr[t];
    float s  = v.x + v.y + v.z + v.w;
    float ss = v.x*v.x + v.y*v.y + v.z*v.z + v.w*v.w;
    #pragma unroll
    for (int off = 16; off >= 1; off >>= 1) {
        s  += __shfl_xor_sync(0xffffffffu, s,  off);
        ss += __shfl_xor_sync(0xffffffffu, ss, off);
    }
    __shared__ float rs[4], rss[4];
    int wid = t >> 5;
    if ((t & 31) == 0) { rs[wid] = s; rss[wid] = ss; }
    __syncthreads();
    s  = rs[0] + rs[1] + rs[2] + rs[3];
    ss = rss[0] + rss[1] + rss[2] + rss[3];
    float mu  = s * (1.0f / 512.0f);
    float var = ss * (1.0f / 512.0f) - mu * mu;
    float r   = rsqrtf(var + 1e-5f);
    float4 w4 = reinterpret_cast<const float4*>(w)[t];
    float4 b4 = reinterpret_cast<const float4*>(b)[t];
    float4 o4;
    o4.x = (v.x - mu) * r * w4.x + b4.x;
    o4.y = (v.y - mu) * r * w4.y + b4.y;
    o4.z = (v.z - mu) * r * w4.z + b4.z;
    o4.w = (v.w - mu) * r * w4.w + b4.w;
    reinterpret_cast<float4*>(y)[(size_t)row * 128 + t] = o4;
}

// ---------------- Generic NT GEMM: C[M,N] = A[M,K] * W[N,K]^T (+bias, relu, resid) ----------------
template<bool RELU, bool RESID>
__global__ void __launch_bounds__(256) gemm_nt(const float* __restrict__ A,
                                               const float* __restrict__ W,
                                               const float* __restrict__ bias,
                                               const float* __restrict__ resid,
                                               float* __restrict__ C,
                                               int M, int N, int K)
{
    const int BK = 32;
    __shared__ float As[BK][132];
    __shared__ float Ws[BK][132];
    int tid = threadIdx.x;
    int bm = blockIdx.y * 128, bn = blockIdx.x * 128;
    int tx = tid & 15, ty = tid >> 4;

    float acc[8][8];
    #pragma unroll
    for (int i = 0; i < 8; i++)
        #pragma unroll
        for (int j = 0; j < 8; j++) acc[i][j] = 0.0f;

    for (int k0 = 0; k0 < K; k0 += BK) {
        #pragma unroll
        for (int it = 0; it < 4; ++it) {
            int idx = tid + it * 256;        // 0..1023
            int row = idx >> 3;
            int kq  = (idx & 7) * 4;
            float4 va = *reinterpret_cast<const float4*>(&A[(size_t)(bm + row) * K + k0 + kq]);
            As[kq + 0][row] = va.x; As[kq + 1][row] = va.y;
            As[kq + 2][row] = va.z; As[kq + 3][row] = va.w;
            float4 vw = *reinterpret_cast<const float4*>(&W[(size_t)(bn + row) * K + k0 + kq]);
            Ws[kq + 0][row] = vw.x; Ws[kq + 1][row] = vw.y;
            Ws[kq + 2][row] = vw.z; Ws[kq + 3][row] = vw.w;
        }
        __syncthreads();
        #pragma unroll
        for (int kk = 0; kk < BK; kk++) {
            float a[8], bb[8];
            *reinterpret_cast<float4*>(a)      = *reinterpret_cast<float4*>(&As[kk][ty * 4]);
            *reinterpret_cast<float4*>(a + 4)  = *reinterpret_cast<float4*>(&As[kk][64 + ty * 4]);
            *reinterpret_cast<float4*>(bb)     = *reinterpret_cast<float4*>(&Ws[kk][tx * 4]);
            *reinterpret_cast<float4*>(bb + 4) = *reinterpret_cast<float4*>(&Ws[kk][64 + tx * 4]);
            #pragma unroll
            for (int i = 0; i < 8; i++)
                #pragma unroll
                for (int j = 0; j < 8; j++)
                    acc[i][j] += a[i] * bb[j];
        }
        __syncthreads();
    }

    float bj[8];
    *reinterpret_cast<float4*>(bj)     = *reinterpret_cast<const float4*>(&bias[bn + tx * 4]);
    *reinterpret_cast<float4*>(bj + 4) = *reinterpret_cast<const float4*>(&bias[bn + 64 + tx * 4]);

    #pragma unroll
    for (int i = 0; i < 8; i++) {
        int r = bm + ((i < 4) ? (ty * 4 + i) : (64 + ty * 4 + i - 4));
        #pragma unroll
        for (int g = 0; g < 2; ++g) {
            int c = bn + g * 64 + tx * 4;
            float4 o;
            o.x = acc[i][g * 4 + 0] + bj[g * 4 + 0];
            o.y = acc[i][g * 4 + 1] + bj[g * 4 + 1];
            o.z = acc[i][g * 4 + 2] + bj[g * 4 + 2];
            o.w = acc[i][g * 4 + 3] + bj[g * 4 + 3];
            if (RELU) {
                o.x = fmaxf(o.x, 0.0f); o.y = fmaxf(o.y, 0.0f);
                o.z = fmaxf(o.z, 0.0f); o.w = fmaxf(o.w, 0.0f);
            }
            if (RESID) {
                float4 rv = *reinterpret_cast<const float4*>(&resid[(size_t)r * N + c]);
                o.x += rv.x; o.y += rv.y; o.z += rv.z; o.w += rv.w;
            }
            *reinterpret_cast<float4*>(&C[(size_t)r * N + c]) = o;
        }
    }
}

// ---------------- RoPE cos/sin table: [SEQ][32] ----------------
__global__ void __launch_bounds__(256) rope_tab_kernel(float2* __restrict__ tab)
{
    int idx = blockIdx.x * 256 + threadIdx.x;   // 0 .. SEQ*32-1
    int s = idx >> 5, i = idx & 31;
    // inv_freq = 1 / 10000^(2i/64); compute in double for a correctly-rounded fp32 value,
    // then round angle to fp32 (matching the reference's fp32 angle), then accurate sincos.
    double freq = 1.0 / pow(10000.0, (double)i / 32.0);
    float ang = (float)((double)s * freq);
    tab[idx] = make_float2(cosf(ang), sinf(ang));
}

// ---------------- split qkv -> Q (rope, pre-scaled), K (rope), V ; layout [B,H,S,D] ----------------
__global__ void __launch_bounds__(256) rope_split_kernel(const float* __restrict__ qkv,
                                                         const float2* __restrict__ tab,
                                                         float* __restrict__ Q,
                                                         float* __restrict__ K,
                                                         float* __restrict__ V)
{
    int idx = blockIdx.x * 256 + threadIdx.x;  // ROWS * 8 heads * 32 pairs
    int d2 = idx & 31;
    int hh = (idx >> 5) & 7;
    int bs = idx >> 8;                 // 0..8191
    int s  = bs & (SEQ - 1);
    int b  = bs >> 12;
    const float* base = qkv + (size_t)bs * 1536 + hh * 64 + d2 * 2;
    float2 q = *reinterpret_cast<const float2*>(base);
    float2 k = *reinterpret_cast<const float2*>(base + 512);
    float2 v = *reinterpret_cast<const float2*>(base + 1024);
    float2 cs = tab[s * 32 + d2];
    size_t o = ((((size_t)b * 8 + hh) * SEQ) + s) * 64 + d2 * 2;
    const float sc = 0.125f;  // 1/sqrt(64), folded into Q
    *reinterpret_cast<float2*>(&Q[o]) =
        make_float2((q.x * cs.x - q.y * cs.y) * sc, (q.x * cs.y + q.y * cs.x) * sc);
    *reinterpret_cast<float2*>(&K[o]) =
        make_float2(k.x * cs.x - k.y * cs.y, k.x * cs.y + k.y * cs.x);
    *reinterpret_cast<float2*>(&V[o]) = v;
}

// ---------------- causal flash attention, fp32, 64x64 tiles ----------------
// smem swizzle: XOR bits [2:4] of col with bits [2:4] of row -> conflict-free float4 LDS
#define SW(r, c) (((r) << 6) + ((c) ^ ((((r) >> 2) & 7) << 2)))

__global__ void __launch_bounds__(256) flash_kernel(const float* __restrict__ Qg,
                                                    const float* __restrict__ Kg,
                                                    const float* __restrict__ Vg,
                                                    float* __restrict__ ctx)
{
    extern __shared__ float sm[];
    float* Qs = sm;             // [d][q] swizzled, 64*64
    float* Ks = sm + 4096;      // [d][k] swizzled
    float* Vs = sm + 8192;      // [k][d] natural
    float* Ps = sm + 12288;     // [k][q] swizzled

    int qt = blockIdx.x;        // q tile 0..63
    int bh = blockIdx.y;        // 0..15
    int b = bh >> 3, hh = bh & 7;
    const float* Qb = Qg + ((size_t)bh * SEQ + qt * 64) * 64;
    const float* Kb = Kg + (size_t)bh * SEQ * 64;
    const float* Vb = Vg + (size_t)bh * SEQ * 64;
    int tid = threadIdx.x, tx = tid & 15, ty = tid >> 4;

    // load Q tile, transposed+swizzled
    #pragma unroll
    for (int it = 0; it < 4; ++it) {
        int idx = tid + it * 256;
        int r = idx >> 4, c = (idx & 15) * 4;
        float4 v = *reinterpret_cast<const float4*>(&Qb[r * 64 + c]);
        Qs[SW(c + 0, r)] = v.x; Qs[SW(c + 1, r)] = v.y;
        Qs[SW(c + 2, r)] = v.z; Qs[SW(c + 3, r)] = v.w;
    }

    float m[4], l[4], o[4][4];
    #pragma unroll
    for (int i = 0; i < 4; i++) {
        m[i] = -1e30f; l[i] = 0.0f;
        #pragma unroll
        for (int j = 0; j < 4; j++) o[i][j] = 0.0f;
    }

    for (int kt = 0; kt <= qt; ++kt) {
        __syncthreads();   // previous iteration done with Ks/Vs/Ps
        #pragma unroll
        for (int it = 0; it < 4; ++it) {
            int idx = tid + it * 256;
            int r = idx >> 4, c = (idx & 15) * 4;
            float4 kv = *reinterpret_cast<const float4*>(&Kb[(kt * 64 + r) * 64 + c]);
            Ks[SW(c + 0, r)] = kv.x; Ks[SW(c + 1, r)] = kv.y;
            Ks[SW(c + 2, r)] = kv.z; Ks[SW(c + 3, r)] = kv.w;
            float4 vv = *reinterpret_cast<const float4*>(&Vb[(kt * 64 + r) * 64 + c]);
            *reinterpret_cast<float4*>(&Vs[r * 64 + c]) = vv;
        }
        __syncthreads();

        // S = Q K^T  (Q pre-scaled)
        float s[4][4];
        #pragma unroll
        for (int i = 0; i < 4; i++)
            #pragma unroll
            for (int j = 0; j < 4; j++) s[i][j] = 0.0f;
        #pragma unroll
        for (int kk = 0; kk < 64; ++kk) {
            float4 qa = *reinterpret_cast<float4*>(&Qs[SW(kk, ty * 4)]);
            float4 kb = *reinterpret_cast<float4*>(&Ks[SW(kk, tx * 4)]);
            float a[4] = {qa.x, qa.y, qa.z, qa.w};
            float c4[4] = {kb.x, kb.y, kb.z, kb.w};
            #pragma unroll
            for (int i = 0; i < 4; i++)
                #pragma unroll
                for (int j = 0; j < 4; j++)
                    s[i][j] += a[i] * c4[j];
        }
        if (kt == qt) {
            #pragma unroll
            for (int i = 0; i < 4; i++)
                #pragma unroll
                for (int j = 0; j < 4; j++)
                    if (tx * 4 + j > ty * 4 + i) s[i][j] = -1e30f;
        }

        // online softmax (row reduce over 16 lanes of same ty)
        #pragma unroll
        for (int i = 0; i < 4; i++) {
            float mx = fmaxf(fmaxf(s[i][0], s[i][1]), fmaxf(s[i][2], s[i][3]));
            #pragma unroll
            for (int off = 8; off >= 1; off >>= 1)
                mx = fmaxf(mx, __shfl_xor_sync(0xffffffffu, mx, off));
            float mn = fmaxf(m[i], mx);
            float al = __expf(m[i] - mn);
            float sum = 0.0f;
            #pragma unroll
            for (int j = 0; j < 4; j++) { s[i][j] = __expf(s[i][j] - mn); sum += s[i][j]; }
            #pragma unroll
            for (int off = 8; off >= 1; off >>= 1)
                sum += __shfl_xor_sync(0xffffffffu, sum, off);
            l[i] = l[i] * al + sum;
            m[i] = mn;
            o[i][0] *= al; o[i][1] *= al; o[i][2] *= al; o[i][3] *= al;
        }

        // write P[k][q] swizzled
        #pragma unroll
        for (int j = 0; j < 4; j++)
            *reinterpret_cast<float4*>(&Ps[SW(tx * 4 + j, ty * 4)]) =
                make_float4(s[0][j], s[1][j], s[2][j], s[3][j]);
        __syncthreads();

        // O += P V
        #pragma unroll
        for (int kk = 0; kk < 64; ++kk) {
            float4 p = *reinterpret_cast<float4*>(&Ps[SW(kk, ty * 4)]);
            float4 v = *reinterpret_cast<float4*>(&Vs[kk * 64 + tx * 4]);
            float pp[4] = {p.x, p.y, p.z, p.w};
            float vv[4] = {v.x, v.y, v.z, v.w};
            #pragma unroll
            for (int i = 0; i < 4; i++)
                #pragma unroll
                for (int j = 0; j < 4; j++)
                    o[i][j] += pp[i] * vv[j];
        }
    }

    // finalize: ctx[b][s][h*64+d]
    #pragma unroll
    for (int i = 0; i < 4; i++) {
        float inv = 1.0f / l[i];
        int srow = qt * 64 + ty * 4 + i;
        size_t off = ((size_t)b * SEQ + srow) * 512 + hh * 64 + tx * 4;
        *reinterpret_cast<float4*>(&ctx[off]) =
            make_float4(o[i][0] * inv, o[i][1] * inv, o[i][2] * inv, o[i][3] * inv);
    }
}

// ---------------- launch ----------------
extern "C" void kernel_launch(void* const* d_in, const int* in_sizes, int n_in,
                              void* d_out, int out_size)
{
    const float* src      = (const float*)d_in[0];
    const float* ln_w     = (const float*)d_in[1];
    const float* ln_b     = (const float*)d_in[2];
    const float* wqkv_w   = (const float*)d_in[3];
    const float* wqkv_b   = (const float*)d_in[4];
    const float* out_w    = (const float*)d_in[5];
    const float* out_b    = (const float*)d_in[6];
    const float* ffn_ln_w = (const float*)d_in[7];
    const float* ffn_ln_b = (const float*)d_in[8];
    const float* ff1_w    = (const float*)d_in[9];
    const float* ff1_b    = (const float*)d_in[10];
    const float* ff2_w    = (const float*)d_in[11];
    const float* ff2_b    = (const float*)d_in[12];
    float* out = (float*)d_out;

    float *xln, *qkv, *Q, *K, *V, *ctx, *src2, *hbuf;
    float2* tab;
    cudaGetSymbolAddress((void**)&xln,  g_xln);
    cudaGetSymbolAddress((void**)&qkv,  g_qkv);
    cudaGetSymbolAddress((void**)&Q,    g_Q);
    cudaGetSymbolAddress((void**)&K,    g_Kv);
    cudaGetSymbolAddress((void**)&V,    g_Vv);
    cudaGetSymbolAddress((void**)&ctx,  g_ctx);
    cudaGetSymbolAddress((void**)&src2, g_src2);
    cudaGetSymbolAddress((void**)&hbuf, g_h);
    cudaGetSymbolAddress((void**)&tab,  g_rope);

    cudaFuncSetAttribute(flash_kernel, cudaFuncAttributeMaxDynamicSharedMemorySize, 65536);

    // 1. LN(src)
    ln_kernel<<<ROWS, 128>>>(src, ln_w, ln_b, xln);
    // 2. QKV projection
    gemm_nt<false, false><<<dim3(12, 64), 256>>>(xln, wqkv_w, wqkv_b, nullptr, qkv,
                                                 ROWS, 3 * D_MODEL, D_MODEL);
    // 3. RoPE table + split/transpose
    rope_tab_kernel<<<(SEQ * 32) / 256, 256>>>(tab);
    rope_split_kernel<<<(ROWS * 8 * 32) / 256, 256>>>(qkv, tab, Q, K, V);
    // 4. causal flash attention
    flash_kernel<<<dim3(SEQ / 64, BH), 256, 65536>>>(Q, K, V, ctx);
    // 5. out projection + residual
    gemm_nt<false, true><<<dim3(4, 64), 256>>>(ctx, out_w, out_b, src, src2,
                                               ROWS, D_MODEL, D_MODEL);
    // 6. LN2
    ln_kernel<<<ROWS, 128>>>(src2, ffn_ln_w, ffn_ln_b, xln);
    // 7. FF1 + relu
    gemm_nt<true, false><<<dim3(16, 64), 256>>>(xln, ff1_w, ff1_b, nullptr, hbuf,
                                                ROWS, D_FF, D_MODEL);
    // 8. FF2 + residual -> out
    gemm_nt<false, true><<<dim3(4, 64), 256>>>(hbuf, ff2_w, ff2_b, src2, out,
                                               ROWS, D_MODEL, D_FF);
}